// round 1
// baseline (speedup 1.0000x reference)
#include <cuda_runtime.h>
#include <cstdint>

#define N_SPLINES 64
#define C_DIM     64
#define T_DIM     68
#define NJ        67          // number of degree-0 intervals
#define TPB       128         // threads per block (main kernel)
#define ROWS_PER_BLOCK (TPB * 2)

// Per-spline piecewise-cubic coefficients, centered at t_j:
// g_Q[(s*T_DIM + j)*4 + d] = d-th Taylor coeff of Q_j at t_j.
__device__ float g_Q[N_SPLINES * T_DIM * 4];

// ---------------------------------------------------------------------------
// Precompute: expand Cox-de Boor into per-interval cubics (fp64, deterministic)
// ---------------------------------------------------------------------------
__device__ __forceinline__ double sinv(double den) {
    return den == 0.0 ? 0.0 : 1.0 / den;
}

// p3[jj][d]: coefficients (monomial, degree<=3) of the piece of N^3_i gated by
// indicator j = i + jj, jj in 0..3.
__device__ __forceinline__ void build_p3(const double* st, int i, double p3[4][4]) {
    double p1[3][2][2];
#pragma unroll
    for (int a2 = 0; a2 < 3; ++a2) {
        int a = i + a2;
        double invA = sinv(st[a + 1] - st[a]);
        double invB = sinv(st[a + 2] - st[a + 1]);
        p1[a2][0][0] = -st[a] * invA;      // left factor:  (x - t_a) * invA
        p1[a2][0][1] = invA;
        p1[a2][1][0] = st[a + 2] * invB;   // right factor: (t_{a+2} - x) * invB
        p1[a2][1][1] = -invB;
    }
    double p2[2][3][3];
#pragma unroll
    for (int a2 = 0; a2 < 2; ++a2) {
        int a = i + a2;
#pragma unroll
        for (int jj = 0; jj < 3; ++jj)
#pragma unroll
            for (int d = 0; d < 3; ++d) p2[a2][jj][d] = 0.0;
        double invA = sinv(st[a + 2] - st[a]);
        double invB = sinv(st[a + 3] - st[a + 1]);
        double l0 = -st[a] * invA, l1 = invA;
        double r0 = st[a + 3] * invB, r1 = -invB;
#pragma unroll
        for (int jj = 0; jj < 2; ++jj)
#pragma unroll
            for (int d = 0; d < 2; ++d) {
                p2[a2][jj][d]     += l0 * p1[a2][jj][d];
                p2[a2][jj][d + 1] += l1 * p1[a2][jj][d];
            }
#pragma unroll
        for (int jj = 1; jj < 3; ++jj)
#pragma unroll
            for (int d = 0; d < 2; ++d) {
                p2[a2][jj][d]     += r0 * p1[a2 + 1][jj - 1][d];
                p2[a2][jj][d + 1] += r1 * p1[a2 + 1][jj - 1][d];
            }
    }
#pragma unroll
    for (int jj = 0; jj < 4; ++jj)
#pragma unroll
        for (int d = 0; d < 4; ++d) p3[jj][d] = 0.0;
    {
        int a = i;
        double invA = sinv(st[a + 3] - st[a]);
        double invB = sinv(st[a + 4] - st[a + 1]);
        double l0 = -st[a] * invA, l1 = invA;
        double r0 = st[a + 4] * invB, r1 = -invB;
#pragma unroll
        for (int jj = 0; jj < 3; ++jj)
#pragma unroll
            for (int d = 0; d < 3; ++d) {
                p3[jj][d]     += l0 * p2[0][jj][d];
                p3[jj][d + 1] += l1 * p2[0][jj][d];
            }
#pragma unroll
        for (int jj = 1; jj < 4; ++jj)
#pragma unroll
            for (int d = 0; d < 3; ++d) {
                p3[jj][d]     += r0 * p2[1][jj - 1][d];
                p3[jj][d + 1] += r1 * p2[1][jj - 1][d];
            }
    }
}

__global__ void precompute_kernel(const float* __restrict__ t,
                                  const float* __restrict__ c) {
    int s = blockIdx.x;
    int tid = threadIdx.x;
    __shared__ double st[T_DIM];
    __shared__ double sc[C_DIM];
    if (tid < T_DIM) st[tid] = (double)t[s * T_DIM + tid];
    if (tid < C_DIM) sc[tid] = (double)c[s * C_DIM + tid];
    __syncthreads();

    if (tid < T_DIM) {
        int j = tid;                      // interval index (j = 67 -> zero pad)
        double b0 = 0.0, b1 = 0.0, b2 = 0.0, b3 = 0.0;
        if (j < NJ) {
            int ilo = (j - 3 < 0) ? 0 : j - 3;
            int ihi = (j < C_DIM - 1) ? j : C_DIM - 1;
            for (int i = ilo; i <= ihi; ++i) {
                double p3[4][4];
                build_p3(st, i, p3);
                int jj = j - i;
                double ci = sc[i];
                b0 += ci * p3[jj][0];
                b1 += ci * p3[jj][1];
                b2 += ci * p3[jj][2];
                b3 += ci * p3[jj][3];
            }
            // Taylor shift: coefficients of Q_j(t_j + u) in u
            double tj = st[j];
            double bb[4] = {b0, b1, b2, b3};
#pragma unroll
            for (int pass = 0; pass < 3; ++pass)
#pragma unroll
                for (int d = 2; d >= 0; --d)
                    if (d >= pass) bb[d] += tj * bb[d + 1];
            b0 = bb[0]; b1 = bb[1]; b2 = bb[2]; b3 = bb[3];
        }
        float* out = &g_Q[(s * T_DIM + j) * 4];
        out[0] = (float)b0;
        out[1] = (float)b1;
        out[2] = (float)b2;
        out[3] = (float)b3;
    }
}

// ---------------------------------------------------------------------------
// Main kernel: S(x) = sum_j [t_j <= x < t_{j+1}] * Horner(Q_j, x - t_j)
// f32x2 packed: each thread evaluates 2 batch rows.
// ---------------------------------------------------------------------------
typedef unsigned long long u64t;

__device__ __forceinline__ u64t pk2(float lo, float hi) {
    u64t r;
    asm("mov.b64 %0, {%1,%2};" : "=l"(r) : "f"(lo), "f"(hi));
    return r;
}
__device__ __forceinline__ void up2(u64t v, float& lo, float& hi) {
    asm("mov.b64 {%0,%1}, %2;" : "=f"(lo), "=f"(hi) : "l"(v));
}
__device__ __forceinline__ u64t add2_(u64t a, u64t b) {
    u64t d;
    asm("add.rn.f32x2 %0, %1, %2;" : "=l"(d) : "l"(a), "l"(b));
    return d;
}
__device__ __forceinline__ u64t fma2_(u64t a, u64t b, u64t c) {
    u64t d;
    asm("fma.rn.f32x2 %0, %1, %2, %3;" : "=l"(d) : "l"(a), "l"(b), "l"(c));
    return d;
}

__global__ __launch_bounds__(TPB)
void bspline_main_kernel(const float* __restrict__ x,
                         const float* __restrict__ t,
                         float* __restrict__ out) {
    __shared__ ulonglong2 sQ01[NJ];     // {q0 dup, q1 dup}
    __shared__ ulonglong2 sQ23[NJ];     // {q2 dup, q3 dup}
    __shared__ u64t       sTn[T_DIM];   // {-t_j, -t_j}

    const int s   = blockIdx.y;
    const int tid = threadIdx.x;

    for (int k = tid; k < T_DIM; k += TPB) {
        float tv = -t[s * T_DIM + k];
        sTn[k] = pk2(tv, tv);
        if (k < NJ) {
            const float* q = &g_Q[(s * T_DIM + k) * 4];
            sQ01[k] = make_ulonglong2(pk2(q[0], q[0]), pk2(q[1], q[1]));
            sQ23[k] = make_ulonglong2(pk2(q[2], q[2]), pk2(q[3], q[3]));
        }
    }
    __syncthreads();

    const int r0 = blockIdx.x * ROWS_PER_BLOCK + tid;
    const int r1 = r0 + TPB;
    const float x0 = x[r0 * N_SPLINES + s];
    const float x1 = x[r1 * N_SPLINES + s];

    const u64t x2 = pk2(x0, x1);
    u64t S = pk2(0.0f, 0.0f);

    u64t dcur = add2_(x2, sTn[0]);      // x - t_0
    float dl, dh;
    up2(dcur, dl, dh);

#pragma unroll 4
    for (int j = 0; j < NJ; ++j) {
        u64t dnext = add2_(x2, sTn[j + 1]);          // x - t_{j+1}
        float dnl, dnh;
        up2(dnext, dnl, dnh);
        // indicator: t_j <= x  &&  x < t_{j+1}  ==  d_j >= 0 && d_{j+1} < 0
        float n0l = (dl >= 0.0f && dnl < 0.0f) ? 1.0f : 0.0f;
        float n0h = (dh >= 0.0f && dnh < 0.0f) ? 1.0f : 0.0f;
        u64t n0 = pk2(n0l, n0h);

        ulonglong2 qa = sQ01[j];
        ulonglong2 qb = sQ23[j];
        u64t h = fma2_(qb.y, dcur, qb.x);            // q3*u + q2
        h = fma2_(h, dcur, qa.y);                    // *u + q1
        h = fma2_(h, dcur, qa.x);                    // *u + q0
        S = fma2_(n0, h, S);                         // gated accumulate

        dcur = dnext; dl = dnl; dh = dnh;
    }

    float s0, s1;
    up2(S, s0, s1);
    out[r0 * N_SPLINES + s] = s0;
    out[r1 * N_SPLINES + s] = s1;
}

// ---------------------------------------------------------------------------
extern "C" void kernel_launch(void* const* d_in, const int* in_sizes, int n_in,
                              void* d_out, int out_size) {
    const float* x = (const float*)d_in[0];   // [B, 64]
    const float* t = (const float*)d_in[1];   // [64, 68]
    const float* c = (const float*)d_in[2];   // [64, 64]
    float* out = (float*)d_out;               // [B, 64]

    const int B = in_sizes[0] / N_SPLINES;    // 65536

    precompute_kernel<<<N_SPLINES, 128>>>(t, c);

    dim3 grid(B / ROWS_PER_BLOCK, N_SPLINES);
    bspline_main_kernel<<<grid, TPB>>>(x, t, out);
}

// round 3
// speedup vs baseline: 1.1881x; 1.1881x over previous
#include <cuda_runtime.h>
#include <cstdint>

#define N_SPLINES 64
#define C_DIM     64
#define T_DIM     68
#define NJ        67              // number of degree-0 intervals
#define TPB       128             // threads per block (main kernel)
#define PACKS     4               // f32x2 packs per thread (8 rows/thread)
#define ROWS_PER_THREAD (2 * PACKS)
#define ROWS_PER_BLOCK  (TPB * ROWS_PER_THREAD)   // 1024

// Per-spline piecewise-cubic coefficients, centered at t_j:
// g_Q[(s*T_DIM + j)*4 + d] = d-th Taylor coeff of Q_j at t_j.
__device__ float g_Q[N_SPLINES * T_DIM * 4];

// ---------------------------------------------------------------------------
// Precompute: expand Cox-de Boor into per-interval cubics (fp64, deterministic)
// Restructured: each basis-function polynomial p3(i) is built exactly once
// (thread i), staged in shared memory, then combined by thread j.
// ---------------------------------------------------------------------------
__device__ __forceinline__ double sinv(double den) {
    return den == 0.0 ? 0.0 : 1.0 / den;
}

// p3[jj][d]: monomial coefficients (degree<=3) of the piece of N^3_i gated by
// indicator j = i + jj, jj in 0..3.
__device__ __forceinline__ void build_p3(const double* st, int i, double p3[4][4]) {
    double p1[3][2][2];
#pragma unroll
    for (int a2 = 0; a2 < 3; ++a2) {
        int a = i + a2;
        double invA = sinv(st[a + 1] - st[a]);
        double invB = sinv(st[a + 2] - st[a + 1]);
        p1[a2][0][0] = -st[a] * invA;
        p1[a2][0][1] = invA;
        p1[a2][1][0] = st[a + 2] * invB;
        p1[a2][1][1] = -invB;
    }
    double p2[2][3][3];
#pragma unroll
    for (int a2 = 0; a2 < 2; ++a2) {
        int a = i + a2;
#pragma unroll
        for (int jj = 0; jj < 3; ++jj)
#pragma unroll
            for (int d = 0; d < 3; ++d) p2[a2][jj][d] = 0.0;
        double invA = sinv(st[a + 2] - st[a]);
        double invB = sinv(st[a + 3] - st[a + 1]);
        double l0 = -st[a] * invA, l1 = invA;
        double r0 = st[a + 3] * invB, r1 = -invB;
#pragma unroll
        for (int jj = 0; jj < 2; ++jj)
#pragma unroll
            for (int d = 0; d < 2; ++d) {
                p2[a2][jj][d]     += l0 * p1[a2][jj][d];
                p2[a2][jj][d + 1] += l1 * p1[a2][jj][d];
            }
#pragma unroll
        for (int jj = 1; jj < 3; ++jj)
#pragma unroll
            for (int d = 0; d < 2; ++d) {
                p2[a2][jj][d]     += r0 * p1[a2 + 1][jj - 1][d];
                p2[a2][jj][d + 1] += r1 * p1[a2 + 1][jj - 1][d];
            }
    }
#pragma unroll
    for (int jj = 0; jj < 4; ++jj)
#pragma unroll
        for (int d = 0; d < 4; ++d) p3[jj][d] = 0.0;
    {
        int a = i;
        double invA = sinv(st[a + 3] - st[a]);
        double invB = sinv(st[a + 4] - st[a + 1]);
        double l0 = -st[a] * invA, l1 = invA;
        double r0 = st[a + 4] * invB, r1 = -invB;
#pragma unroll
        for (int jj = 0; jj < 3; ++jj)
#pragma unroll
            for (int d = 0; d < 3; ++d) {
                p3[jj][d]     += l0 * p2[0][jj][d];
                p3[jj][d + 1] += l1 * p2[0][jj][d];
            }
#pragma unroll
        for (int jj = 1; jj < 4; ++jj)
#pragma unroll
            for (int d = 0; d < 3; ++d) {
                p3[jj][d]     += r0 * p2[1][jj - 1][d];
                p3[jj][d + 1] += r1 * p2[1][jj - 1][d];
            }
    }
}

__global__ void precompute_kernel(const float* __restrict__ t,
                                  const float* __restrict__ c) {
    int s = blockIdx.x;
    int tid = threadIdx.x;
    __shared__ double st[T_DIM];
    __shared__ double sc[C_DIM];
    __shared__ double sP[C_DIM][4][4];   // p3 per basis function i
    if (tid < T_DIM) st[tid] = (double)t[s * T_DIM + tid];
    if (tid < C_DIM) sc[tid] = (double)c[s * C_DIM + tid];
    __syncthreads();

    // Phase 1: thread i builds p3(i) once.
    if (tid < C_DIM) {
        double p3[4][4];
        build_p3(st, tid, p3);
#pragma unroll
        for (int jj = 0; jj < 4; ++jj)
#pragma unroll
            for (int d = 0; d < 4; ++d) sP[tid][jj][d] = p3[jj][d];
    }
    __syncthreads();

    // Phase 2: thread j combines the <=4 overlapping pieces, Taylor-shifts.
    if (tid < T_DIM) {
        int j = tid;                      // interval index (j = 67 -> zero pad)
        double bb[4] = {0.0, 0.0, 0.0, 0.0};
        if (j < NJ) {
            int ilo = (j - 3 < 0) ? 0 : j - 3;
            int ihi = (j < C_DIM - 1) ? j : C_DIM - 1;
            for (int i = ilo; i <= ihi; ++i) {
                int jj = j - i;
                double ci = sc[i];
#pragma unroll
                for (int d = 0; d < 4; ++d) bb[d] += ci * sP[i][jj][d];
            }
            // Taylor shift: coefficients of Q_j(t_j + u) in u
            double tj = st[j];
#pragma unroll
            for (int pass = 0; pass < 3; ++pass)
#pragma unroll
                for (int d = 2; d >= 0; --d)
                    if (d >= pass) bb[d] += tj * bb[d + 1];
        }
        float* out = &g_Q[(s * T_DIM + j) * 4];
        out[0] = (float)bb[0];
        out[1] = (float)bb[1];
        out[2] = (float)bb[2];
        out[3] = (float)bb[3];
    }
}

// ---------------------------------------------------------------------------
// Main kernel: S(x) = sum_j [t_j <= x < t_{j+1}] * Horner(Q_j, x - t_j)
// f32x2 packed, PACKS packs (2*PACKS rows) per thread: the 3 broadcast LDS
// per j-iteration are amortized over 8 rows.
// ---------------------------------------------------------------------------
typedef unsigned long long u64t;

__device__ __forceinline__ u64t pk2(float lo, float hi) {
    u64t r;
    asm("mov.b64 %0, {%1,%2};" : "=l"(r) : "f"(lo), "f"(hi));
    return r;
}
__device__ __forceinline__ void up2(u64t v, float& lo, float& hi) {
    asm("mov.b64 {%0,%1}, %2;" : "=f"(lo), "=f"(hi) : "l"(v));
}
__device__ __forceinline__ u64t add2_(u64t a, u64t b) {
    u64t d;
    asm("add.rn.f32x2 %0, %1, %2;" : "=l"(d) : "l"(a), "l"(b));
    return d;
}
__device__ __forceinline__ u64t fma2_(u64t a, u64t b, u64t c) {
    u64t d;
    asm("fma.rn.f32x2 %0, %1, %2, %3;" : "=l"(d) : "l"(a), "l"(b), "l"(c));
    return d;
}

__global__ __launch_bounds__(TPB)
void bspline_main_kernel(const float* __restrict__ x,
                         const float* __restrict__ t,
                         float* __restrict__ out) {
    __shared__ ulonglong2 sQ01[NJ];     // {q0 dup, q1 dup}
    __shared__ ulonglong2 sQ23[NJ];     // {q2 dup, q3 dup}
    __shared__ u64t       sTn[T_DIM];   // {-t_j, -t_j}

    const int s   = blockIdx.y;
    const int tid = threadIdx.x;

    for (int k = tid; k < T_DIM; k += TPB) {
        float tv = -t[s * T_DIM + k];
        sTn[k] = pk2(tv, tv);
        if (k < NJ) {
            const float* q = &g_Q[(s * T_DIM + k) * 4];
            sQ01[k] = make_ulonglong2(pk2(q[0], q[0]), pk2(q[1], q[1]));
            sQ23[k] = make_ulonglong2(pk2(q[2], q[2]), pk2(q[3], q[3]));
        }
    }
    __syncthreads();

    const int rbase = blockIdx.x * ROWS_PER_BLOCK + tid;

    // Load 8 x values (2 per pack)
    float xl[PACKS], xh[PACKS];
    u64t  x2[PACKS];
#pragma unroll
    for (int p = 0; p < PACKS; ++p) {
        xl[p] = x[(rbase + (2 * p)     * TPB) * N_SPLINES + s];
        xh[p] = x[(rbase + (2 * p + 1) * TPB) * N_SPLINES + s];
        x2[p] = pk2(xl[p], xh[p]);
    }

    u64t  S[PACKS];
    u64t  d[PACKS];
    float dl[PACKS], dh[PACKS];
#pragma unroll
    for (int p = 0; p < PACKS; ++p) {
        S[p] = pk2(0.0f, 0.0f);
        d[p] = add2_(x2[p], sTn[0]);     // x - t_0
        up2(d[p], dl[p], dh[p]);
    }

#pragma unroll 2
    for (int j = 0; j < NJ; ++j) {
        const u64t tn = sTn[j + 1];
        const ulonglong2 qa = sQ01[j];
        const ulonglong2 qb = sQ23[j];
#pragma unroll
        for (int p = 0; p < PACKS; ++p) {
            u64t dn = add2_(x2[p], tn);              // x - t_{j+1}
            float dnl, dnh;
            up2(dn, dnl, dnh);

            u64t h = fma2_(qb.y, d[p], qb.x);        // q3*u + q2
            h = fma2_(h, d[p], qa.y);                // *u + q1
            h = fma2_(h, d[p], qa.x);                // *u + q0
            float hl, hh;
            up2(h, hl, hh);

            // indicator: t_j <= x && x < t_{j+1}  ==  d_j >= 0 && d_{j+1} < 0
            float gl = (dl[p] >= 0.0f && dnl < 0.0f) ? hl : 0.0f;
            float gh = (dh[p] >= 0.0f && dnh < 0.0f) ? hh : 0.0f;
            S[p] = add2_(S[p], pk2(gl, gh));

            d[p] = dn; dl[p] = dnl; dh[p] = dnh;
        }
    }

#pragma unroll
    for (int p = 0; p < PACKS; ++p) {
        float s0, s1;
        up2(S[p], s0, s1);
        out[(rbase + (2 * p)     * TPB) * N_SPLINES + s] = s0;
        out[(rbase + (2 * p + 1) * TPB) * N_SPLINES + s] = s1;
    }
}

// ---------------------------------------------------------------------------
extern "C" void kernel_launch(void* const* d_in, const int* in_sizes, int n_in,
                              void* d_out, int out_size) {
    const float* x = (const float*)d_in[0];   // [B, 64]
    const float* t = (const float*)d_in[1];   // [64, 68]
    const float* c = (const float*)d_in[2];   // [64, 64]
    float* out = (float*)d_out;               // [B, 64]

    const int B = in_sizes[0] / N_SPLINES;    // 65536

    precompute_kernel<<<N_SPLINES, 128>>>(t, c);

    dim3 grid(B / ROWS_PER_BLOCK, N_SPLINES);
    bspline_main_kernel<<<grid, TPB>>>(x, t, out);
}

// round 4
// speedup vs baseline: 3.1782x; 2.6752x over previous
#include <cuda_runtime.h>
#include <cstdint>

#define N_SPLINES 64
#define C_DIM     64
#define T_DIM     68
#define NJ        67
#define NTH       (2*NJ)      // 134 thresholds per spline
#define NPF       (NTH + 1)   // 135 prefix polynomials (m = 0..134)

// Precomputed per-spline tables
__device__ float  g_th [N_SPLINES][NTH];   // sorted thresholds
__device__ float  g_ctr[N_SPLINES][NPF];   // center of prefix poly m (= th[m-1], 0 for m=0)
__device__ float4 g_C  [N_SPLINES][NPF];   // Taylor coeffs {c0,c1,c2,c3} of prefix poly m

// ---------------------------------------------------------------------------
// Precompute (fp64): Cox-de Boor -> per-interval cubics -> threshold
// decomposition -> sort -> prefix-sum polys -> Taylor-center each prefix.
// ---------------------------------------------------------------------------
__device__ __forceinline__ double sinv(double den) {
    return den == 0.0 ? 0.0 : 1.0 / den;
}

// p3[jj][d]: monomial coefficients (deg<=3) of the piece of N^3_i gated by
// indicator j = i + jj, jj in 0..3.  (Validated in R1-R3: rel_err 2.8e-7.)
__device__ __forceinline__ void build_p3(const double* st, int i, double p3[4][4]) {
    double p1[3][2][2];
#pragma unroll
    for (int a2 = 0; a2 < 3; ++a2) {
        int a = i + a2;
        double invA = sinv(st[a + 1] - st[a]);
        double invB = sinv(st[a + 2] - st[a + 1]);
        p1[a2][0][0] = -st[a] * invA;
        p1[a2][0][1] = invA;
        p1[a2][1][0] = st[a + 2] * invB;
        p1[a2][1][1] = -invB;
    }
    double p2[2][3][3];
#pragma unroll
    for (int a2 = 0; a2 < 2; ++a2) {
        int a = i + a2;
#pragma unroll
        for (int jj = 0; jj < 3; ++jj)
#pragma unroll
            for (int d = 0; d < 3; ++d) p2[a2][jj][d] = 0.0;
        double invA = sinv(st[a + 2] - st[a]);
        double invB = sinv(st[a + 3] - st[a + 1]);
        double l0 = -st[a] * invA, l1 = invA;
        double r0 = st[a + 3] * invB, r1 = -invB;
#pragma unroll
        for (int jj = 0; jj < 2; ++jj)
#pragma unroll
            for (int d = 0; d < 2; ++d) {
                p2[a2][jj][d]     += l0 * p1[a2][jj][d];
                p2[a2][jj][d + 1] += l1 * p1[a2][jj][d];
            }
#pragma unroll
        for (int jj = 1; jj < 3; ++jj)
#pragma unroll
            for (int d = 0; d < 2; ++d) {
                p2[a2][jj][d]     += r0 * p1[a2 + 1][jj - 1][d];
                p2[a2][jj][d + 1] += r1 * p1[a2 + 1][jj - 1][d];
            }
    }
#pragma unroll
    for (int jj = 0; jj < 4; ++jj)
#pragma unroll
        for (int d = 0; d < 4; ++d) p3[jj][d] = 0.0;
    {
        int a = i;
        double invA = sinv(st[a + 3] - st[a]);
        double invB = sinv(st[a + 4] - st[a + 1]);
        double l0 = -st[a] * invA, l1 = invA;
        double r0 = st[a + 4] * invB, r1 = -invB;
#pragma unroll
        for (int jj = 0; jj < 3; ++jj)
#pragma unroll
            for (int d = 0; d < 3; ++d) {
                p3[jj][d]     += l0 * p2[0][jj][d];
                p3[jj][d + 1] += l1 * p2[0][jj][d];
            }
#pragma unroll
        for (int jj = 1; jj < 4; ++jj)
#pragma unroll
            for (int d = 0; d < 3; ++d) {
                p3[jj][d]     += r0 * p2[1][jj - 1][d];
                p3[jj][d + 1] += r1 * p2[1][jj - 1][d];
            }
    }
}

__global__ void precompute_kernel(const float* __restrict__ t,
                                  const float* __restrict__ c) {
    const int s   = blockIdx.x;
    const int tid = threadIdx.x;

    __shared__ double st[T_DIM];
    __shared__ double sc[C_DIM];
    __shared__ double sP[C_DIM][4][4];    // p3 per basis i
    __shared__ double qm[NJ][4];          // monomial Q_j
    __shared__ float  thr[NTH];           // unsorted thresholds
    __shared__ float  sth[NTH];           // sorted thresholds
    __shared__ int    sidx[NTH];          // sorted -> original k
    __shared__ double sv[NTH][4];         // signed pieces -> inclusive prefix

    if (tid < T_DIM) st[tid] = (double)t[s * T_DIM + tid];
    if (tid < C_DIM) sc[tid] = (double)c[s * C_DIM + tid];
    __syncthreads();

    // A1: thread i builds p3(i) once
    if (tid < C_DIM) {
        double p3[4][4];
        build_p3(st, tid, p3);
#pragma unroll
        for (int jj = 0; jj < 4; ++jj)
#pragma unroll
            for (int d = 0; d < 4; ++d) sP[tid][jj][d] = p3[jj][d];
    }
    __syncthreads();

    // A2: thread j combines overlapping pieces -> monomial Q_j
    if (tid < NJ) {
        int j = tid;
        double bb[4] = {0.0, 0.0, 0.0, 0.0};
        int ilo = (j - 3 < 0) ? 0 : j - 3;
        int ihi = (j < C_DIM - 1) ? j : C_DIM - 1;
        for (int i = ilo; i <= ihi; ++i) {
            int jj = j - i;
            double ci = sc[i];
#pragma unroll
            for (int d = 0; d < 4; ++d) bb[d] += ci * sP[i][jj][d];
        }
#pragma unroll
        for (int d = 0; d < 4; ++d) qm[j][d] = bb[d];
    }

    // B: thresholds. k<67: theta=t_k, poly +Q_k; k>=67: theta=max(t_{k-67},t_{k-66}), poly -Q_{k-67}
    if (tid < NTH) {
        if (tid < NJ) thr[tid] = t[s * T_DIM + tid];
        else {
            int j = tid - NJ;
            thr[tid] = fmaxf(t[s * T_DIM + j], t[s * T_DIM + j + 1]);
        }
    }
    __syncthreads();

    // C: rank sort (stable)
    if (tid < NTH) {
        float v = thr[tid];
        int r = 0;
        for (int i = 0; i < NTH; ++i) {
            float w = thr[i];
            r += (w < v) || (w == v && i < tid);
        }
        sth[r] = v;
        sidx[r] = tid;
    }
    __syncthreads();

    // D: signed pieces in sorted order, then inclusive Hillis-Steele scan
    if (tid < NTH) {
        int k = sidx[tid];
        int p = (k < NJ) ? k : k - NJ;
        double sgn = (k < NJ) ? 1.0 : -1.0;
#pragma unroll
        for (int d = 0; d < 4; ++d) sv[tid][d] = sgn * qm[p][d];
    }
    __syncthreads();
    for (int stp = 1; stp < NTH; stp <<= 1) {
        double tmp[4] = {0.0, 0.0, 0.0, 0.0};
        bool act = (tid < NTH) && (tid >= stp);
        if (act) {
#pragma unroll
            for (int d = 0; d < 4; ++d) tmp[d] = sv[tid - stp][d];
        }
        __syncthreads();
        if (act) {
#pragma unroll
            for (int d = 0; d < 4; ++d) sv[tid][d] += tmp[d];
        }
        __syncthreads();
    }
    // prefix poly for count m (m>=1) is sv[m-1]

    // E: Taylor-center prefix poly m at sth[m-1]; write fp32 tables
    if (tid <= NTH) {
        int m = tid;
        float4 oc = make_float4(0.f, 0.f, 0.f, 0.f);
        float  ctr = 0.f;
        if (m > 0) {
            double bb[4];
#pragma unroll
            for (int d = 0; d < 4; ++d) bb[d] = sv[m - 1][d];
            double tc = (double)sth[m - 1];
#pragma unroll
            for (int pass = 0; pass < 3; ++pass)
#pragma unroll
                for (int d = 2; d >= 0; --d)
                    if (d >= pass) bb[d] += tc * bb[d + 1];
            oc = make_float4((float)bb[0], (float)bb[1], (float)bb[2], (float)bb[3]);
            ctr = sth[m - 1];
        }
        g_C[s][m] = oc;
        g_ctr[s][m] = ctr;
    }
    if (tid < NTH) g_th[s][tid] = sth[tid];
}

// ---------------------------------------------------------------------------
// Main kernel: binary search for m = #{theta <= x}, then one cubic Horner.
// Warp lanes = 32 consecutive splines (coalesced x/out); warps = rows.
// ---------------------------------------------------------------------------
#define THC_STRIDE 271   // odd word stride: th[0..133], ctr at [134..268]
#define C_STRIDE   137   // float4 stride

extern __shared__ float dynsmem[];

__global__ __launch_bounds__(1024, 2)
void bspline_main_kernel(const float* __restrict__ x,
                         float* __restrict__ out, int B) {
    float*  sThC = dynsmem;                                  // 32*271 floats
    float4* sC   = (float4*)(dynsmem + 32 * THC_STRIDE);     // 32*137 float4 (16B aligned: 34688B)

    const int tid   = threadIdx.x;
    const int sBase = blockIdx.y * 32;

    for (int i = tid; i < 32 * NTH; i += 1024) {
        int sp = i / NTH, k = i - sp * NTH;
        sThC[sp * THC_STRIDE + k] = g_th[sBase + sp][k];
    }
    for (int i = tid; i < 32 * NPF; i += 1024) {
        int sp = i / NPF, k = i - sp * NPF;
        sThC[sp * THC_STRIDE + NTH + k] = g_ctr[sBase + sp][k];
    }
    for (int i = tid; i < 32 * NPF; i += 1024) {
        int sp = i / NPF, k = i - sp * NPF;
        sC[sp * C_STRIDE + k] = g_C[sBase + sp][k];
    }
    __syncthreads();

    const int lane = tid & 31;
    const int warp = tid >> 5;
    const float*  tb = &sThC[lane * THC_STRIDE];
    const float4* cb = &sC[lane * C_STRIDE];
    const int col = sBase + lane;
    const int wstride = gridDim.x * 32;

    for (int row = blockIdx.x * 32 + warp; row < B; row += wstride) {
        float xv = x[row * N_SPLINES + col];

        // branchless upper_bound over 134 sorted thresholds (8 steps + final)
        int base = 0;
        base += (tb[base + 66] <= xv) ? 67 : 0;   // n 134 -> 67
        base += (tb[base + 32] <= xv) ? 33 : 0;   // 67 -> 34
        base += (tb[base + 16] <= xv) ? 17 : 0;   // 34 -> 17
        base += (tb[base + 7]  <= xv) ? 8  : 0;   // 17 -> 9
        base += (tb[base + 3]  <= xv) ? 4  : 0;   // 9  -> 5
        base += (tb[base + 1]  <= xv) ? 2  : 0;   // 5  -> 3
        base += (tb[base]      <= xv) ? 1  : 0;   // 3  -> 2
        base += (tb[base]      <= xv) ? 1  : 0;   // 2  -> 1
        int m = base + ((tb[base] <= xv) ? 1 : 0);

        float4 cf = cb[m];
        float  u  = xv - tb[NTH + m];
        out[row * N_SPLINES + col] =
            fmaf(fmaf(fmaf(cf.w, u, cf.z), u, cf.y), u, cf.x);
    }
}

// ---------------------------------------------------------------------------
extern "C" void kernel_launch(void* const* d_in, const int* in_sizes, int n_in,
                              void* d_out, int out_size) {
    const float* x = (const float*)d_in[0];   // [B, 64]
    const float* t = (const float*)d_in[1];   // [64, 68]
    const float* c = (const float*)d_in[2];   // [64, 64]
    float* out = (float*)d_out;               // [B, 64]

    const int B = in_sizes[0] / N_SPLINES;    // 65536

    precompute_kernel<<<N_SPLINES, 256>>>(t, c);

    const size_t smemSz = (size_t)(32 * THC_STRIDE) * 4 + (size_t)(32 * C_STRIDE) * 16; // 104,832 B
    cudaFuncSetAttribute(bspline_main_kernel,
                         cudaFuncAttributeMaxDynamicSharedMemorySize, (int)smemSz);

    dim3 grid(148, 2);   // 296 blocks, 2 per SM, lanes cover splines [32*by, 32*by+32)
    bspline_main_kernel<<<grid, 1024, smemSz>>>(x, out, B);
}

// round 5
// speedup vs baseline: 3.3245x; 1.0460x over previous
#include <cuda_runtime.h>
#include <cstdint>
#include <math_constants.h>

#define N_SPLINES 64
#define C_DIM     64
#define T_DIM     68
#define NJ        67
#define NTH       (2*NJ)      // 134 thresholds per spline
#define NPF       (NTH + 1)   // 135 prefix polynomials (m = 0..134)
#define NB        256         // buckets
#define BKT_LO    (-4.0f)
#define BKT_SCALE (32.0f)

// Precomputed per-spline tables
// g_th layout: [0] = -INF, [1..134] = sorted thresholds, [135] = +INF
__device__ float   g_th[N_SPLINES][NTH + 2];
__device__ float4  g_C [N_SPLINES][NPF];     // Taylor coeffs of prefix poly m
__device__ uint8_t g_bt[N_SPLINES][NB];      // bucket -> #{th < edge_b}

// ---------------------------------------------------------------------------
// Precompute (fp64): Cox-de Boor -> per-interval cubics -> threshold
// decomposition -> sort -> prefix polys -> Taylor-center -> bucket table.
// ---------------------------------------------------------------------------
__device__ __forceinline__ double sinv(double den) {
    return den == 0.0 ? 0.0 : 1.0 / den;
}

__device__ __forceinline__ void build_p3(const double* st, int i, double p3[4][4]) {
    double p1[3][2][2];
#pragma unroll
    for (int a2 = 0; a2 < 3; ++a2) {
        int a = i + a2;
        double invA = sinv(st[a + 1] - st[a]);
        double invB = sinv(st[a + 2] - st[a + 1]);
        p1[a2][0][0] = -st[a] * invA;
        p1[a2][0][1] = invA;
        p1[a2][1][0] = st[a + 2] * invB;
        p1[a2][1][1] = -invB;
    }
    double p2[2][3][3];
#pragma unroll
    for (int a2 = 0; a2 < 2; ++a2) {
        int a = i + a2;
#pragma unroll
        for (int jj = 0; jj < 3; ++jj)
#pragma unroll
            for (int d = 0; d < 3; ++d) p2[a2][jj][d] = 0.0;
        double invA = sinv(st[a + 2] - st[a]);
        double invB = sinv(st[a + 3] - st[a + 1]);
        double l0 = -st[a] * invA, l1 = invA;
        double r0 = st[a + 3] * invB, r1 = -invB;
#pragma unroll
        for (int jj = 0; jj < 2; ++jj)
#pragma unroll
            for (int d = 0; d < 2; ++d) {
                p2[a2][jj][d]     += l0 * p1[a2][jj][d];
                p2[a2][jj][d + 1] += l1 * p1[a2][jj][d];
            }
#pragma unroll
        for (int jj = 1; jj < 3; ++jj)
#pragma unroll
            for (int d = 0; d < 2; ++d) {
                p2[a2][jj][d]     += r0 * p1[a2 + 1][jj - 1][d];
                p2[a2][jj][d + 1] += r1 * p1[a2 + 1][jj - 1][d];
            }
    }
#pragma unroll
    for (int jj = 0; jj < 4; ++jj)
#pragma unroll
        for (int d = 0; d < 4; ++d) p3[jj][d] = 0.0;
    {
        int a = i;
        double invA = sinv(st[a + 3] - st[a]);
        double invB = sinv(st[a + 4] - st[a + 1]);
        double l0 = -st[a] * invA, l1 = invA;
        double r0 = st[a + 4] * invB, r1 = -invB;
#pragma unroll
        for (int jj = 0; jj < 3; ++jj)
#pragma unroll
            for (int d = 0; d < 3; ++d) {
                p3[jj][d]     += l0 * p2[0][jj][d];
                p3[jj][d + 1] += l1 * p2[0][jj][d];
            }
#pragma unroll
        for (int jj = 1; jj < 4; ++jj)
#pragma unroll
            for (int d = 0; d < 3; ++d) {
                p3[jj][d]     += r0 * p2[1][jj - 1][d];
                p3[jj][d + 1] += r1 * p2[1][jj - 1][d];
            }
    }
}

__global__ void precompute_kernel(const float* __restrict__ t,
                                  const float* __restrict__ c) {
    const int s   = blockIdx.x;
    const int tid = threadIdx.x;

    __shared__ double st[T_DIM];
    __shared__ double sc[C_DIM];
    __shared__ double sP[C_DIM][4][4];
    __shared__ double qm[NJ][4];
    __shared__ float  thr[NTH];
    __shared__ float  sth[NTH];
    __shared__ int    sidx[NTH];
    __shared__ double sv[NTH][4];

    if (tid < T_DIM) st[tid] = (double)t[s * T_DIM + tid];
    if (tid < C_DIM) sc[tid] = (double)c[s * C_DIM + tid];
    __syncthreads();

    // A1: thread i builds p3(i)
    if (tid < C_DIM) {
        double p3[4][4];
        build_p3(st, tid, p3);
#pragma unroll
        for (int jj = 0; jj < 4; ++jj)
#pragma unroll
            for (int d = 0; d < 4; ++d) sP[tid][jj][d] = p3[jj][d];
    }
    __syncthreads();

    // A2: thread j combines pieces -> monomial Q_j
    if (tid < NJ) {
        int j = tid;
        double bb[4] = {0.0, 0.0, 0.0, 0.0};
        int ilo = (j - 3 < 0) ? 0 : j - 3;
        int ihi = (j < C_DIM - 1) ? j : C_DIM - 1;
        for (int i = ilo; i <= ihi; ++i) {
            int jj = j - i;
            double ci = sc[i];
#pragma unroll
            for (int d = 0; d < 4; ++d) bb[d] += ci * sP[i][jj][d];
        }
#pragma unroll
        for (int d = 0; d < 4; ++d) qm[j][d] = bb[d];
    }

    // B: thresholds
    if (tid < NTH) {
        if (tid < NJ) thr[tid] = t[s * T_DIM + tid];
        else {
            int j = tid - NJ;
            thr[tid] = fmaxf(t[s * T_DIM + j], t[s * T_DIM + j + 1]);
        }
    }
    __syncthreads();

    // C: rank sort (stable)
    if (tid < NTH) {
        float v = thr[tid];
        int r = 0;
        for (int i = 0; i < NTH; ++i) {
            float w = thr[i];
            r += (w < v) || (w == v && i < tid);
        }
        sth[r] = v;
        sidx[r] = tid;
    }
    __syncthreads();

    // D: signed pieces, inclusive scan
    if (tid < NTH) {
        int k = sidx[tid];
        int p = (k < NJ) ? k : k - NJ;
        double sgn = (k < NJ) ? 1.0 : -1.0;
#pragma unroll
        for (int d = 0; d < 4; ++d) sv[tid][d] = sgn * qm[p][d];
    }
    __syncthreads();
    for (int stp = 1; stp < NTH; stp <<= 1) {
        double tmp[4] = {0.0, 0.0, 0.0, 0.0};
        bool act = (tid < NTH) && (tid >= stp);
        if (act) {
#pragma unroll
            for (int d = 0; d < 4; ++d) tmp[d] = sv[tid - stp][d];
        }
        __syncthreads();
        if (act) {
#pragma unroll
            for (int d = 0; d < 4; ++d) sv[tid][d] += tmp[d];
        }
        __syncthreads();
    }

    // E: Taylor-center prefix poly m at sth[m-1]
    if (tid <= NTH) {
        int m = tid;
        float4 oc = make_float4(0.f, 0.f, 0.f, 0.f);
        if (m > 0) {
            double bb[4];
#pragma unroll
            for (int d = 0; d < 4; ++d) bb[d] = sv[m - 1][d];
            double tc = (double)sth[m - 1];
#pragma unroll
            for (int pass = 0; pass < 3; ++pass)
#pragma unroll
                for (int d = 2; d >= 0; --d)
                    if (d >= pass) bb[d] += tc * bb[d + 1];
            oc = make_float4((float)bb[0], (float)bb[1], (float)bb[2], (float)bb[3]);
        }
        g_C[s][m] = oc;
    }
    // F: padded sorted thresholds
    if (tid < NTH) g_th[s][tid + 1] = sth[tid];
    if (tid == 0) {
        g_th[s][0]       = -CUDART_INF_F;
        g_th[s][NTH + 1] =  CUDART_INF_F;
    }
    // G: bucket table  bt[b] = #{th < edge_b},  edge_b = LO + b/SCALE
    if (tid < NB) {
        float edge = BKT_LO + (float)tid * (1.0f / BKT_SCALE);
        int cnt = 0;
        for (int i = 0; i < NTH; ++i) cnt += (sth[i] < edge);
        g_bt[s][tid] = (uint8_t)cnt;
    }
}

// ---------------------------------------------------------------------------
// Main kernel: bucket lookup -> sentinel-guarded scans -> one cubic Horner.
// Warp lanes = 32 consecutive splines (coalesced x/out); warps = rows.
// ---------------------------------------------------------------------------
#define TH_STRIDE 139   // floats per spline (136 used), odd for bank spread
#define C_STRIDE  137   // float4 per spline (135 used), odd
#define BT_STRIDE 260   // bytes per spline (256 used), 65 words

extern __shared__ float dynsmem[];

__global__ __launch_bounds__(1024, 2)
void bspline_main_kernel(const float* __restrict__ x,
                         float* __restrict__ out, int B) {
    float*   sTh = dynsmem;                                   // 32*139 floats
    float4*  sC  = (float4*)(dynsmem + 32 * TH_STRIDE);       // 32*137 float4
    uint8_t* sBt = (uint8_t*)(sC + 32 * C_STRIDE);            // 32*260 bytes

    const int tid   = threadIdx.x;
    const int sBase = blockIdx.y * 32;

    for (int i = tid; i < 32 * (NTH + 2); i += 1024) {
        int sp = i / (NTH + 2), k = i - sp * (NTH + 2);
        sTh[sp * TH_STRIDE + k] = g_th[sBase + sp][k];
    }
    for (int i = tid; i < 32 * NPF; i += 1024) {
        int sp = i / NPF, k = i - sp * NPF;
        sC[sp * C_STRIDE + k] = g_C[sBase + sp][k];
    }
    for (int i = tid; i < 32 * NB; i += 1024) {
        int sp = i >> 8, k = i & 255;
        sBt[sp * BT_STRIDE + k] = g_bt[sBase + sp][k];
    }
    __syncthreads();

    const int lane = tid & 31;
    const int warp = tid >> 5;
    const float*   tb1 = &sTh[lane * TH_STRIDE];    // tb1[m] = th[m-1]; tb1[0]=-INF, tb1[135]=+INF
    const float4*  cb  = &sC[lane * C_STRIDE];
    const uint8_t* btb = &sBt[lane * BT_STRIDE];
    const int col = sBase + lane;
    const int wstride = gridDim.x * 32;

    for (int row = blockIdx.x * 32 + warp; row < B; row += wstride) {
        float xv = x[row * N_SPLINES + col];

        // bucket estimate (any value in [0,255] is corrected by the scans)
        int b = (int)((xv - BKT_LO) * BKT_SCALE);
        b = min(max(b, 0), NB - 1);
        int m = (int)btb[b];

        // down-correct (rare): th[m-1] must be <= xv ; tb1[0] = -INF terminates
        while (tb1[m] > xv) --m;
        // up-scan: count thresholds <= xv ; tb1[135] = +INF terminates
        while (tb1[m + 1] <= xv) ++m;

        float v   = tb1[m];                      // th[m-1] (or -INF at m=0)
        float ctr = (m > 0) ? v : 0.0f;          // m=0 poly is zero; avoid INF*0
        float4 cf = cb[m];
        float  u  = xv - ctr;
        out[row * N_SPLINES + col] =
            fmaf(fmaf(fmaf(cf.w, u, cf.z), u, cf.y), u, cf.x);
    }
}

// ---------------------------------------------------------------------------
extern "C" void kernel_launch(void* const* d_in, const int* in_sizes, int n_in,
                              void* d_out, int out_size) {
    const float* x = (const float*)d_in[0];   // [B, 64]
    const float* t = (const float*)d_in[1];   // [64, 68]
    const float* c = (const float*)d_in[2];   // [64, 64]
    float* out = (float*)d_out;               // [B, 64]

    const int B = in_sizes[0] / N_SPLINES;    // 65536

    precompute_kernel<<<N_SPLINES, 256>>>(t, c);

    const size_t smemSz = (size_t)(32 * TH_STRIDE) * 4
                        + (size_t)(32 * C_STRIDE) * 16
                        + (size_t)(32 * BT_STRIDE);          // 96,256 B
    cudaFuncSetAttribute(bspline_main_kernel,
                         cudaFuncAttributeMaxDynamicSharedMemorySize, (int)smemSz);

    dim3 grid(148, 2);
    bspline_main_kernel<<<grid, 1024, smemSz>>>(x, out, B);
}